// round 14
// baseline (speedup 1.0000x reference)
#include <cuda_runtime.h>
#include <cstdint>

// Problem constants
#define LDIM   128
#define RDIM   2048
#define EDIM   32
#define FDIM   64
#define KTOT   2048
#define BATCH  8

// Tiling: CTA = 128L x 128R x (ECH*64)k, 512 threads, thread tile 8L x 4R
#define KT       16
#define RT       128
#define ECH      4
#define NSTAGE   ((ECH*FDIM)/KT)     // 16
#define NTHREADS 512
#define LDSROW   132                 // padded tile row (words)
#define ZROW     132                 // zb padded row (words)

// rbf(d,e) = exp(-((d-mu_e)/sigma)^2) = 2^(-(KC*(d-mu_e))^2)
#define KC_CONST   3.2029930899845557f
#define MU_STEP    (12.0f/31.0f)

// dynamic smem layout (floats)
#define SM_A      0
#define SM_B      (2*KT*LDSROW)                // 4224
#define SM_ZB     (SM_B + 2*KT*LDSROW)         // 8448
#define SM_FLOATS (SM_ZB + LDIM*ZROW)          // 25344
#define SMEM_BYTES (SM_FLOATS*4)               // 101376 B

__device__ __forceinline__ unsigned long long dup2(float x) {
    unsigned long long r;
    unsigned int u = __float_as_uint(x);
    asm("mov.b64 %0, {%1, %1};" : "=l"(r) : "r"(u));
    return r;
}
__device__ __forceinline__ void fma2(unsigned long long &acc,
                                     unsigned long long a,
                                     unsigned long long b) {
    asm("fma.rn.f32x2 %0, %1, %2, %0;" : "+l"(acc) : "l"(a), "l"(b));
}
__device__ __forceinline__ void unpack2(unsigned long long v, float &lo, float &hi) {
    unsigned int a, b;
    asm("mov.b64 {%0, %1}, %2;" : "=r"(a), "=r"(b) : "l"(v));
    lo = __uint_as_float(a);
    hi = __uint_as_float(b);
}
__device__ __forceinline__ float ex2a(float x) {
    float r; asm("ex2.approx.ftz.f32 %0, %1;" : "=f"(r) : "f"(x)); return r;
}
__device__ __forceinline__ float sqrta(float x) {
    float r; asm("sqrt.approx.f32 %0, %1;" : "=f"(r) : "f"(x)); return r;
}

__global__ void ff_init_kernel(float* out) {
    if (threadIdx.x < BATCH) out[threadIdx.x] = 0.0f;
}

__global__ void __launch_bounds__(NTHREADS, 1)
ff_main_kernel(const float* __restrict__ ligf,
               const float* __restrict__ recf,
               const float* __restrict__ ligc,
               const float* __restrict__ recc,
               float* __restrict__ out)
{
    extern __shared__ __align__(16) float smem[];
    float* As = smem + SM_A;
    float* Bs = smem + SM_B;
    float* zb = smem + SM_ZB;

    const int tid  = threadIdx.x;
    const int lane = tid & 31;          // owns r = 4*lane .. 4*lane+3
    const int w    = tid >> 5;          // 0..15; owns l = w*8 .. w*8+7
    const int l0   = w * 8;

    const int rt = blockIdx.x;          // 0..15
    const int ec = blockIdx.y;          // 0..7
    const int b  = blockIdx.z;          // 0..7

    const int r0    = rt * RT;
    const int e0    = ec * ECH;
    const int kbase = e0 * FDIM;

    const float* Ag = ligf + (size_t)b * LDIM * KTOT + kbase;
    const float* Bg = recf + ((size_t)b * RDIM + r0) * KTOT + kbase;

    // staging: each thread one float4 (4 consecutive k) per tile per stage
    const int srow = tid >> 2;          // 0..127
    const int scol = (tid & 3) * 4;     // 0,4,8,12

    // ---- stage coords into smem (tile area, overwritten later) ----
    {
        float* lc = As;                 // [128][3]
        float* rc = As + 512;           // [128][3]
        for (int i = tid; i < LDIM * 3; i += NTHREADS)
            lc[i] = ligc[(size_t)b * LDIM * 3 + i];
        for (int i = tid; i < RT * 3; i += NTHREADS)
            rc[i] = recc[((size_t)b * RDIM + r0) * 3 + i];
        __syncthreads();

        // zb[l][r] = KC * dist(l, r0+r): 32 entries per thread
        const int l  = tid >> 2;            // 0..127
        const int rq = (tid & 3) * 32;      // r block of 32
        const float lx = lc[l * 3], ly = lc[l * 3 + 1], lz = lc[l * 3 + 2];
        float zbuf[32];
        const float* rcp = rc + rq * 3;
        #pragma unroll 8
        for (int i = 0; i < 32; i++) {
            float dx = lx - rcp[i * 3], dy = ly - rcp[i * 3 + 1],
                  dz = lz - rcp[i * 3 + 2];
            float dd = fmaf(dx, dx, fmaf(dy, dy, dz * dz));
            zbuf[i] = KC_CONST * sqrta(dd);
        }
        __syncthreads();                // coords consumed; safe to overwrite As
        float* zrow = zb + l * ZROW + rq;
        #pragma unroll 8
        for (int i = 0; i < 32; i++) zrow[i] = zbuf[i];
    }

    // acc[p][j] = packed {l = l0+2p, l0+2p+1} x r = 4*lane+j
    unsigned long long acc[4][4];
    #pragma unroll
    for (int p = 0; p < 4; p++)
        #pragma unroll
        for (int j = 0; j < 4; j++)
            acc[p][j] = 0ULL;

    float u_acc = 0.0f;

    // ---- prefetch stage 0 ----
    float4 pa, pb;
    pa = *(const float4*)(Ag + (size_t)srow * KTOT + scol);
    pb = *(const float4*)(Bg + (size_t)srow * KTOT + scol);

    #pragma unroll 1
    for (int s = 0; s < NSTAGE; s++) {
        const int buf = s & 1;
        float* Asb = As + buf * (KT * LDSROW);
        float* Bsb = Bs + buf * (KT * LDSROW);

        // store staged tile FIRST (R7 ordering)
        {
            float va[4] = {pa.x, pa.y, pa.z, pa.w};
            float vb[4] = {pb.x, pb.y, pb.z, pb.w};
            #pragma unroll
            for (int j = 0; j < 4; j++) {
                Asb[(scol + j) * LDSROW + srow] = va[j];
                Bsb[(scol + j) * LDSROW + srow] = vb[j];
            }
        }
        __syncthreads();

        // issue next-stage LDG immediately (lands during compute)
        if (s + 1 < NSTAGE) {
            const int ko = (s + 1) * KT + scol;
            pa = *(const float4*)(Ag + (size_t)srow * KTOT + ko);
            pb = *(const float4*)(Bg + (size_t)srow * KTOT + ko);
        }

        // ---- main compute: KT k-steps with operand double-buffering ----
        unsigned long long a2c[4];
        float4 bfc;
        {
            const ulonglong2* Ar = (const ulonglong2*)(Asb + l0);
            ulonglong2 t0 = Ar[0];
            ulonglong2 t1 = Ar[1];
            a2c[0] = t0.x; a2c[1] = t0.y; a2c[2] = t1.x; a2c[3] = t1.y;
            bfc = *(const float4*)(Bsb + 4 * lane);
        }
        #pragma unroll
        for (int k = 0; k < KT; k++) {
            unsigned long long a2n[4];
            float4 bfn;
            if (k + 1 < KT) {
                const ulonglong2* Ar =
                    (const ulonglong2*)(Asb + (k + 1) * LDSROW + l0);
                ulonglong2 t0 = Ar[0];
                ulonglong2 t1 = Ar[1];
                a2n[0] = t0.x; a2n[1] = t0.y; a2n[2] = t1.x; a2n[3] = t1.y;
                bfn = *(const float4*)(Bsb + (k + 1) * LDSROW + 4 * lane);
            }

            unsigned long long b2[4];
            b2[0] = dup2(bfc.x);
            b2[1] = dup2(bfc.y);
            b2[2] = dup2(bfc.z);
            b2[3] = dup2(bfc.w);

            #pragma unroll
            for (int p = 0; p < 4; p++)
                #pragma unroll
                for (int j = 0; j < 4; j++)
                    fma2(acc[p][j], a2c[p], b2[j]);

            if (k + 1 < KT) {
                a2c[0] = a2n[0]; a2c[1] = a2n[1];
                a2c[2] = a2n[2]; a2c[3] = a2n[3];
                bfc = bfn;
            }
        }

        // ---- epilogue fold at each e boundary (every 4 stages) ----
        if ((s & 3) == 3) {
            const int e = e0 + (s >> 2);
            const float c2 = KC_CONST * MU_STEP * (float)e;
            #pragma unroll
            for (int p = 0; p < 4; p++) {
                float4 za = *(const float4*)(zb + (l0 + 2 * p) * ZROW + 4 * lane);
                float4 zc = *(const float4*)(zb + (l0 + 2 * p + 1) * ZROW + 4 * lane);
                float z0v[4] = {za.x, za.y, za.z, za.w};
                float z1v[4] = {zc.x, zc.y, zc.z, zc.w};
                #pragma unroll
                for (int j = 0; j < 4; j++) {
                    float dot0, dot1;
                    unpack2(acc[p][j], dot0, dot1);
                    float q0 = z0v[j] - c2;
                    float q1 = z1v[j] - c2;
                    u_acc = fmaf(ex2a(-q0 * q0), dot0, u_acc);
                    u_acc = fmaf(ex2a(-q1 * q1), dot1, u_acc);
                    acc[p][j] = 0ULL;
                }
            }
        }
    }

    // ---- block reduction + atomic accumulate into U[b] ----
    #pragma unroll
    for (int o = 16; o > 0; o >>= 1)
        u_acc += __shfl_xor_sync(0xffffffffu, u_acc, o);

    __syncthreads();
    float* red = smem;
    if (lane == 0) red[w] = u_acc;
    __syncthreads();
    if (tid == 0) {
        float ssum = 0.0f;
        #pragma unroll
        for (int ww = 0; ww < NTHREADS / 32; ww++) ssum += red[ww];
        atomicAdd(out + b, ssum * 0.01f);   // ENERGY_SCALE
    }
}

extern "C" void kernel_launch(void* const* d_in, const int* in_sizes, int n_in,
                              void* d_out, int out_size) {
    (void)in_sizes; (void)n_in; (void)out_size;
    const float* lig_feat  = (const float*)d_in[0];
    const float* rec_feat  = (const float*)d_in[1];
    const float* lig_coord = (const float*)d_in[2];
    const float* rec_coord = (const float*)d_in[3];
    float* out = (float*)d_out;

    cudaFuncSetAttribute(ff_main_kernel,
                         cudaFuncAttributeMaxDynamicSharedMemorySize,
                         SMEM_BYTES);

    ff_init_kernel<<<1, 32>>>(out);

    // (16, 8, 8) = 1024 CTAs, 1 per SM
    dim3 grid(RDIM / RT, EDIM / ECH, BATCH);
    ff_main_kernel<<<grid, NTHREADS, SMEM_BYTES>>>(lig_feat, rec_feat,
                                                   lig_coord, rec_coord, out);
}